// round 1
// baseline (speedup 1.0000x reference)
#include <cuda_runtime.h>
#include <math.h>

// Problem constants
#define BB 4
#define LL 1024
#define HH 512
#define NHEAD 8
#define DD 64
#define MTOT (BB * LL)   // 4096

// Scratch (device globals — no allocation allowed)
__device__ float g_q[BB * LL * HH];
__device__ float g_k[BB * LL * HH];
__device__ float g_v[BB * LL * HH];
__device__ float g_att[BB * LL * HH];

// ---------------------------------------------------------------------------
// GEMM body: Y[M,N] = X[M,K] @ W[N,K]^T + bias,  M=4096, N=512, K=512
// Block tile 128x128, BK=32, 256 threads, 8x8 per thread as 2x2 strips of 4.
// ---------------------------------------------------------------------------
__device__ __forceinline__ void gemm_xwt_body(
    const float* __restrict__ X, const float* __restrict__ W,
    const float* __restrict__ bias, float* __restrict__ Y,
    int bx, int by)
{
    __shared__ float As[32][128];   // k-major (transposed): As[k][row]
    __shared__ float Bs[32][128];   // k-major: Bs[k][col]

    const int tid = threadIdx.x;
    const int tx = tid & 15;
    const int ty = tid >> 4;
    const int row0 = by * 128;
    const int col0 = bx * 128;

    float acc[2][2][4][4];
#pragma unroll
    for (int ri = 0; ri < 2; ri++)
#pragma unroll
        for (int ci = 0; ci < 2; ci++)
#pragma unroll
            for (int i = 0; i < 4; i++)
#pragma unroll
                for (int j = 0; j < 4; j++)
                    acc[ri][ci][i][j] = 0.f;

    const int lr = tid >> 3;          // 0..31 : row within a 32-row pass
    const int lk = (tid & 7) << 2;    // 0,4,...,28 : k offset (float4)

    for (int k0 = 0; k0 < 512; k0 += 32) {
#pragma unroll
        for (int p = 0; p < 4; p++) {
            int r = (p << 5) + lr;
            float4 a = *reinterpret_cast<const float4*>(
                &X[(size_t)(row0 + r) * 512 + k0 + lk]);
            As[lk + 0][r] = a.x; As[lk + 1][r] = a.y;
            As[lk + 2][r] = a.z; As[lk + 3][r] = a.w;
            float4 b = *reinterpret_cast<const float4*>(
                &W[(size_t)(col0 + r) * 512 + k0 + lk]);
            Bs[lk + 0][r] = b.x; Bs[lk + 1][r] = b.y;
            Bs[lk + 2][r] = b.z; Bs[lk + 3][r] = b.w;
        }
        __syncthreads();

#pragma unroll 8
        for (int kk = 0; kk < 32; kk++) {
            float4 a0 = *reinterpret_cast<const float4*>(&As[kk][(ty << 2)]);
            float4 a1 = *reinterpret_cast<const float4*>(&As[kk][64 + (ty << 2)]);
            float4 b0 = *reinterpret_cast<const float4*>(&Bs[kk][(tx << 2)]);
            float4 b1 = *reinterpret_cast<const float4*>(&Bs[kk][64 + (tx << 2)]);
            float av[2][4] = {{a0.x, a0.y, a0.z, a0.w}, {a1.x, a1.y, a1.z, a1.w}};
            float bv[2][4] = {{b0.x, b0.y, b0.z, b0.w}, {b1.x, b1.y, b1.z, b1.w}};
#pragma unroll
            for (int ri = 0; ri < 2; ri++)
#pragma unroll
                for (int ci = 0; ci < 2; ci++)
#pragma unroll
                    for (int i = 0; i < 4; i++)
#pragma unroll
                        for (int j = 0; j < 4; j++)
                            acc[ri][ci][i][j] += av[ri][i] * bv[ci][j];
        }
        __syncthreads();
    }

    // epilogue: + bias, vectorized store
#pragma unroll
    for (int ri = 0; ri < 2; ri++)
#pragma unroll
        for (int i = 0; i < 4; i++) {
            int row = row0 + (ri << 6) + (ty << 2) + i;
#pragma unroll
            for (int ci = 0; ci < 2; ci++) {
                int col = col0 + (ci << 6) + (tx << 2);
                float4 bb = *reinterpret_cast<const float4*>(&bias[col]);
                float4 o;
                o.x = acc[ri][ci][i][0] + bb.x;
                o.y = acc[ri][ci][i][1] + bb.y;
                o.z = acc[ri][ci][i][2] + bb.z;
                o.w = acc[ri][ci][i][3] + bb.w;
                *reinterpret_cast<float4*>(&Y[(size_t)row * 512 + col]) = o;
            }
        }
}

__global__ __launch_bounds__(256, 2)
void proj3_kernel(const float* __restrict__ q_in, const float* __restrict__ k_in,
                  const float* __restrict__ v_in,
                  const float* __restrict__ wq, const float* __restrict__ bq,
                  const float* __restrict__ wk, const float* __restrict__ bk,
                  const float* __restrict__ wv, const float* __restrict__ bv)
{
    const float* X; const float* W; const float* bias; float* Y;
    if (blockIdx.z == 0)      { X = q_in; W = wq; bias = bq; Y = g_q; }
    else if (blockIdx.z == 1) { X = k_in; W = wk; bias = bk; Y = g_k; }
    else                      { X = v_in; W = wv; bias = bv; Y = g_v; }
    gemm_xwt_body(X, W, bias, Y, blockIdx.x, blockIdx.y);
}

__global__ __launch_bounds__(256, 2)
void ff_kernel(const float* __restrict__ w, const float* __restrict__ bias,
               float* __restrict__ out)
{
    gemm_xwt_body(g_att, w, bias, out, blockIdx.x, blockIdx.y);
}

// ---------------------------------------------------------------------------
// Fused attention: per (b, h, 64-row q-tile). Online softmax, key-tile loop
// truncated at ceil(len/64) (masked tiles fully skipped — saves FLOPs and
// the rel_pos_embedding bandwidth).
// ---------------------------------------------------------------------------
__global__ __launch_bounds__(256, 1)
void attn_kernel(const float* __restrict__ rel,
                 const int* __restrict__ seq_len,
                 const int* __restrict__ lex_num)
{
    __shared__ float Qs[64][64];    // d-major: Qs[d][qr]
    __shared__ float KPs[64][64];   // K d-major Ks[d][kr]; reused as P: Ps[kk][qr]
    __shared__ float Vs[64][64];    // Vs[kr][d]

    const int qt = blockIdx.x;
    const int h  = blockIdx.y;
    const int b  = blockIdx.z;
    const int tid = threadIdx.x;
    const int tx = tid & 15;
    const int ty = tid >> 4;

    const int len = seq_len[b] + lex_num[b];
    int ntiles = (len + 63) >> 6;
    if (ntiles > 16) ntiles = 16;

    // Load Q tile transposed into smem (d-major)
    const float* Qg = g_q + (size_t)b * (LL * HH) + (size_t)h * DD;
    {
        const int c = tid & 15;
        const int rb = tid >> 4;
#pragma unroll
        for (int p = 0; p < 4; p++) {
            int r = (p << 4) + rb;
            float4 v = *reinterpret_cast<const float4*>(
                &Qg[(size_t)(qt * 64 + r) * HH + (c << 2)]);
            int d0 = c << 2;
            Qs[d0 + 0][r] = v.x; Qs[d0 + 1][r] = v.y;
            Qs[d0 + 2][r] = v.z; Qs[d0 + 3][r] = v.w;
        }
    }

    float m_i[4], l_i[4], o[4][4];
#pragma unroll
    for (int i = 0; i < 4; i++) {
        m_i[i] = -1e30f; l_i[i] = 0.f;
#pragma unroll
        for (int j = 0; j < 4; j++) o[i][j] = 0.f;
    }

    const float* Kg = g_k + (size_t)b * (LL * HH) + (size_t)h * DD;
    const float* Vg = g_v + (size_t)b * (LL * HH) + (size_t)h * DD;
    const float* relb = rel + (((size_t)b * NHEAD + h) * LL + (size_t)qt * 64) * LL;

    for (int kt = 0; kt < ntiles; kt++) {
        __syncthreads();   // prior PV reads of KPs/Vs complete before overwrite
        {
            const int c = tid & 15;
            const int rb = tid >> 4;
#pragma unroll
            for (int p = 0; p < 4; p++) {
                int r = (p << 4) + rb;
                int d0 = c << 2;
                float4 kv = *reinterpret_cast<const float4*>(
                    &Kg[(size_t)(kt * 64 + r) * HH + d0]);
                KPs[d0 + 0][r] = kv.x; KPs[d0 + 1][r] = kv.y;
                KPs[d0 + 2][r] = kv.z; KPs[d0 + 3][r] = kv.w;
                float4 vv = *reinterpret_cast<const float4*>(
                    &Vg[(size_t)(kt * 64 + r) * HH + d0]);
                *reinterpret_cast<float4*>(&Vs[r][d0]) = vv;
            }
        }
        __syncthreads();

        // S = Q @ K^T  (64x64x64)
        float s[4][4];
#pragma unroll
        for (int i = 0; i < 4; i++)
#pragma unroll
            for (int j = 0; j < 4; j++) s[i][j] = 0.f;

#pragma unroll 8
        for (int d = 0; d < 64; d++) {
            float4 a  = *reinterpret_cast<const float4*>(&Qs[d][(ty << 2)]);
            float4 bf = *reinterpret_cast<const float4*>(&KPs[d][(tx << 2)]);
            float av[4] = {a.x, a.y, a.z, a.w};
            float bv[4] = {bf.x, bf.y, bf.z, bf.w};
#pragma unroll
            for (int i = 0; i < 4; i++)
#pragma unroll
                for (int j = 0; j < 4; j++) s[i][j] += av[i] * bv[j];
        }

        // scale + rel_pos + key-padding mask
        const int colbase = kt * 64 + (tx << 2);
#pragma unroll
        for (int i = 0; i < 4; i++) {
            int qr = (ty << 2) + i;
            float4 rv = *reinterpret_cast<const float4*>(
                &relb[(size_t)qr * LL + colbase]);
            float rvv[4] = {rv.x, rv.y, rv.z, rv.w};
#pragma unroll
            for (int j = 0; j < 4; j++) {
                s[i][j] = s[i][j] * 0.125f + rvv[j];
                if (colbase + j >= len) s[i][j] = -1e30f;
            }
        }

        // online softmax update (row stats live in 16-lane half-warp groups)
#pragma unroll
        for (int i = 0; i < 4; i++) {
            float mx = fmaxf(fmaxf(s[i][0], s[i][1]), fmaxf(s[i][2], s[i][3]));
#pragma unroll
            for (int off = 8; off > 0; off >>= 1)
                mx = fmaxf(mx, __shfl_xor_sync(0xffffffffu, mx, off));
            float mnew = fmaxf(m_i[i], mx);
            float corr = __expf(m_i[i] - mnew);
            m_i[i] = mnew;
            float sum = 0.f;
#pragma unroll
            for (int j = 0; j < 4; j++) {
                s[i][j] = __expf(s[i][j] - mnew);
                sum += s[i][j];
            }
#pragma unroll
            for (int off = 8; off > 0; off >>= 1)
                sum += __shfl_xor_sync(0xffffffffu, sum, off);
            l_i[i] = l_i[i] * corr + sum;
#pragma unroll
            for (int j = 0; j < 4; j++) o[i][j] *= corr;
        }

        __syncthreads();   // everyone done reading K from KPs
        // write P transposed into KPs: Ps[kcol][qrow]
#pragma unroll
        for (int i = 0; i < 4; i++)
#pragma unroll
            for (int j = 0; j < 4; j++)
                KPs[(tx << 2) + j][(ty << 2) + i] = s[i][j];
        __syncthreads();

        // O += P @ V  (64x64x64)
#pragma unroll 8
        for (int kk = 0; kk < 64; kk++) {
            float4 a  = *reinterpret_cast<const float4*>(&KPs[kk][(ty << 2)]);
            float4 bf = *reinterpret_cast<const float4*>(&Vs[kk][(tx << 2)]);
            float av[4] = {a.x, a.y, a.z, a.w};
            float bv[4] = {bf.x, bf.y, bf.z, bf.w};
#pragma unroll
            for (int i = 0; i < 4; i++)
#pragma unroll
                for (int j = 0; j < 4; j++) o[i][j] += av[i] * bv[j];
        }
    }

    // normalize + store
    float* Og = g_att + (size_t)b * (LL * HH) + (size_t)h * DD;
#pragma unroll
    for (int i = 0; i < 4; i++) {
        float inv = 1.0f / l_i[i];
        float4 ov;
        ov.x = o[i][0] * inv; ov.y = o[i][1] * inv;
        ov.z = o[i][2] * inv; ov.w = o[i][3] * inv;
        *reinterpret_cast<float4*>(
            &Og[(size_t)(qt * 64 + (ty << 2) + i) * HH + (tx << 2)]) = ov;
    }
}

// ---------------------------------------------------------------------------
extern "C" void kernel_launch(void* const* d_in, const int* in_sizes, int n_in,
                              void* d_out, int out_size)
{
    const float* key   = (const float*)d_in[0];
    const float* query = (const float*)d_in[1];
    const float* value = (const float*)d_in[2];
    const float* rel   = (const float*)d_in[3];
    const float* wk_w  = (const float*)d_in[4];
    const float* wk_b  = (const float*)d_in[5];
    const float* wq_w  = (const float*)d_in[6];
    const float* wq_b  = (const float*)d_in[7];
    const float* wv_w  = (const float*)d_in[8];
    const float* wv_b  = (const float*)d_in[9];
    const float* ff_w  = (const float*)d_in[10];
    const float* ff_b  = (const float*)d_in[11];
    const int* seq_len = (const int*)d_in[12];
    const int* lex_num = (const int*)d_in[13];
    float* out = (float*)d_out;

    // Q/K/V projections in one launch (z selects which)
    proj3_kernel<<<dim3(4, 32, 3), 256>>>(query, key, value,
                                          wq_w, wq_b, wk_w, wk_b, wv_w, wv_b);
    // fused attention (rel bias + mask + softmax + PV)
    attn_kernel<<<dim3(16, NHEAD, BB), 256>>>(rel, seq_len, lex_num);
    // output projection
    ff_kernel<<<dim3(4, 32), 256>>>(ff_w, ff_b, out);
}

// round 4
// speedup vs baseline: 1.4992x; 1.4992x over previous
#include <cuda_runtime.h>
#include <math.h>
#include <stdint.h>

// Problem constants
#define BB 4
#define LL 1024
#define HH 512
#define NHEAD 8
#define DD 64

// Scratch (device globals — no allocation allowed)
__device__ float g_q[BB * LL * HH];
__device__ float g_k[BB * LL * HH];
__device__ float g_v[BB * LL * HH];
__device__ float g_att[BB * LL * HH];

// ===========================================================================
// Helpers
// ===========================================================================
__device__ __forceinline__ uint32_t smem_u32(const void* p) {
    return (uint32_t)__cvta_generic_to_shared(p);
}
__device__ __forceinline__ void cp_async16(uint32_t dst, const void* src) {
    asm volatile("cp.async.cg.shared.global [%0], [%1], 16;"
                 :: "r"(dst), "l"(src) : "memory");
}
#define CP_COMMIT() asm volatile("cp.async.commit_group;" ::: "memory")

__device__ __forceinline__ uint32_t f2tf32(float x) {
    uint32_t r;
    asm("cvt.rna.tf32.f32 %0, %1;" : "=r"(r) : "f"(x));
    return r;
}
__device__ __forceinline__ void mma_tf32(float* d, const uint32_t* a, const uint32_t* b) {
    asm volatile(
        "mma.sync.aligned.m16n8k8.row.col.f32.tf32.tf32.f32 "
        "{%0,%1,%2,%3}, {%4,%5,%6,%7}, {%8,%9}, {%0,%1,%2,%3};"
        : "+f"(d[0]), "+f"(d[1]), "+f"(d[2]), "+f"(d[3])
        : "r"(a[0]), "r"(a[1]), "r"(a[2]), "r"(a[3]), "r"(b[0]), "r"(b[1]));
}

// ===========================================================================
// tf32 mma.sync GEMM:  Y[M,512] = X[M,512] @ W[512,512]^T + bias
// CTA tile 128x128, 8 warps (2x4), warp tile 64x32, BK=32, double-buffered
// cp.async. Smem pitch 36 floats -> conflict-free fragment LDS.
// ===========================================================================
#define BK 32
#define PITCH 36
#define STAGE_F (128 * PITCH)          // floats per operand per stage
#define DYN_SMEM (4 * STAGE_F * 4)     // 2 ops x 2 stages = 73728 B

__device__ __forceinline__ void gemm_mma_body(
    const float* __restrict__ X, const float* __restrict__ W,
    const float* __restrict__ bias, float* __restrict__ Y,
    int bx, int by)
{
    extern __shared__ float sm[];
    float* As[2] = { sm,               sm + STAGE_F };
    float* Bs[2] = { sm + 2 * STAGE_F, sm + 3 * STAGE_F };

    const int tid  = threadIdx.x;
    const int w    = tid >> 5;
    const int lane = tid & 31;
    const int lr   = lane >> 2;        // 0..7
    const int lc   = lane & 3;         // 0..3
    const int wm   = (w >> 2) * 64;    // warp m offset
    const int wn   = (w & 3) * 32;     // warp n offset
    const int row0 = by * 128;
    const int col0 = bx * 128;

    float acc[4][4][4];
#pragma unroll
    for (int i = 0; i < 4; i++)
#pragma unroll
        for (int j = 0; j < 4; j++)
#pragma unroll
            for (int t = 0; t < 4; t++) acc[i][j][t] = 0.f;

    // ---- stage loader (1024 16B chunks per operand pair, 4 per thread each)
#define LOAD_STAGE(IT)                                                        \
    do {                                                                      \
        const int s_  = (IT) & 1;                                             \
        const int k0_ = (IT) * BK;                                            \
        _Pragma("unroll")                                                     \
        for (int p = 0; p < 4; p++) {                                         \
            int id = tid + (p << 8);                                          \
            int r = id >> 3, c = id & 7;                                      \
            cp_async16(smem_u32(&As[s_][r * PITCH + c * 4]),                  \
                       &X[(size_t)(row0 + r) * 512 + k0_ + c * 4]);           \
        }                                                                     \
        _Pragma("unroll")                                                     \
        for (int p = 0; p < 4; p++) {                                         \
            int id = tid + (p << 8);                                          \
            int r = id >> 3, c = id & 7;                                      \
            cp_async16(smem_u32(&Bs[s_][r * PITCH + c * 4]),                  \
                       &W[(size_t)(col0 + r) * 512 + k0_ + c * 4]);           \
        }                                                                     \
        CP_COMMIT();                                                          \
    } while (0)

    LOAD_STAGE(0);

    for (int it = 0; it < 16; it++) {
        if (it + 1 < 16) {
            LOAD_STAGE(it + 1);
            asm volatile("cp.async.wait_group 1;" ::: "memory");
        } else {
            asm volatile("cp.async.wait_group 0;" ::: "memory");
        }
        __syncthreads();

        const float* A = As[it & 1];
        const float* B = Bs[it & 1];
#pragma unroll
        for (int kk = 0; kk < BK; kk += 8) {
            uint32_t a[4][4], b[4][2];
#pragma unroll
            for (int i = 0; i < 4; i++) {
                const float* ap = &A[(wm + i * 16 + lr) * PITCH + kk + lc];
                a[i][0] = f2tf32(ap[0]);
                a[i][1] = f2tf32(ap[8 * PITCH]);
                a[i][2] = f2tf32(ap[4]);
                a[i][3] = f2tf32(ap[8 * PITCH + 4]);
            }
#pragma unroll
            for (int j = 0; j < 4; j++) {
                const float* bp = &B[(wn + j * 8 + lr) * PITCH + kk + lc];
                b[j][0] = f2tf32(bp[0]);
                b[j][1] = f2tf32(bp[4]);
            }
#pragma unroll
            for (int i = 0; i < 4; i++)
#pragma unroll
                for (int j = 0; j < 4; j++)
                    mma_tf32(acc[i][j], a[i], b[j]);
        }
        __syncthreads();
    }

    // ---- epilogue: +bias, float2 stores
#pragma unroll
    for (int j = 0; j < 4; j++) {
        const int col = col0 + wn + j * 8 + lc * 2;
        const float2 bb = *reinterpret_cast<const float2*>(&bias[col]);
#pragma unroll
        for (int i = 0; i < 4; i++) {
            const int r0 = row0 + wm + i * 16 + lr;
            float2 o0 = { acc[i][j][0] + bb.x, acc[i][j][1] + bb.y };
            float2 o1 = { acc[i][j][2] + bb.x, acc[i][j][3] + bb.y };
            *reinterpret_cast<float2*>(&Y[(size_t)r0 * 512 + col]) = o0;
            *reinterpret_cast<float2*>(&Y[(size_t)(r0 + 8) * 512 + col]) = o1;
        }
    }
#undef LOAD_STAGE
}

__global__ __launch_bounds__(256, 1)
void proj3_mma_kernel(const float* __restrict__ q_in, const float* __restrict__ k_in,
                      const float* __restrict__ v_in,
                      const float* __restrict__ wq, const float* __restrict__ bq,
                      const float* __restrict__ wk, const float* __restrict__ bk,
                      const float* __restrict__ wv, const float* __restrict__ bv)
{
    const float* X; const float* W; const float* bias; float* Y;
    if (blockIdx.z == 0)      { X = q_in; W = wq; bias = bq; Y = g_q; }
    else if (blockIdx.z == 1) { X = k_in; W = wk; bias = bk; Y = g_k; }
    else                      { X = v_in; W = wv; bias = bv; Y = g_v; }
    gemm_mma_body(X, W, bias, Y, blockIdx.x, blockIdx.y);
}

__global__ __launch_bounds__(256, 1)
void ff_mma_kernel(const float* __restrict__ w, const float* __restrict__ bias,
                   float* __restrict__ out)
{
    gemm_mma_body(g_att, w, bias, out, blockIdx.x, blockIdx.y);
}

// ---------------------------------------------------------------------------
// Fused attention (UNCHANGED from round-1 passing version): per (b,h,64-row
// q-tile), online softmax, key tiles past len skipped entirely.
// ---------------------------------------------------------------------------
__global__ __launch_bounds__(256, 1)
void attn_kernel(const float* __restrict__ rel,
                 const int* __restrict__ seq_len,
                 const int* __restrict__ lex_num)
{
    __shared__ float Qs[64][64];    // d-major: Qs[d][qr]
    __shared__ float KPs[64][64];   // K d-major Ks[d][kr]; reused as P: Ps[kk][qr]
    __shared__ float Vs[64][64];    // Vs[kr][d]

    const int qt = blockIdx.x;
    const int h  = blockIdx.y;
    const int b  = blockIdx.z;
    const int tid = threadIdx.x;
    const int tx = tid & 15;
    const int ty = tid >> 4;

    const int len = seq_len[b] + lex_num[b];
    int ntiles = (len + 63) >> 6;
    if (ntiles > 16) ntiles = 16;

    const float* Qg = g_q + (size_t)b * (LL * HH) + (size_t)h * DD;
    {
        const int c = tid & 15;
        const int rb = tid >> 4;
#pragma unroll
        for (int p = 0; p < 4; p++) {
            int r = (p << 4) + rb;
            float4 v = *reinterpret_cast<const float4*>(
                &Qg[(size_t)(qt * 64 + r) * HH + (c << 2)]);
            int d0 = c << 2;
            Qs[d0 + 0][r] = v.x; Qs[d0 + 1][r] = v.y;
            Qs[d0 + 2][r] = v.z; Qs[d0 + 3][r] = v.w;
        }
    }

    float m_i[4], l_i[4], o[4][4];
#pragma unroll
    for (int i = 0; i < 4; i++) {
        m_i[i] = -1e30f; l_i[i] = 0.f;
#pragma unroll
        for (int j = 0; j < 4; j++) o[i][j] = 0.f;
    }

    const float* Kg = g_k + (size_t)b * (LL * HH) + (size_t)h * DD;
    const float* Vg = g_v + (size_t)b * (LL * HH) + (size_t)h * DD;
    const float* relb = rel + (((size_t)b * NHEAD + h) * LL + (size_t)qt * 64) * LL;

    for (int kt = 0; kt < ntiles; kt++) {
        __syncthreads();
        {
            const int c = tid & 15;
            const int rb = tid >> 4;
#pragma unroll
            for (int p = 0; p < 4; p++) {
                int r = (p << 4) + rb;
                int d0 = c << 2;
                float4 kv = *reinterpret_cast<const float4*>(
                    &Kg[(size_t)(kt * 64 + r) * HH + d0]);
                KPs[d0 + 0][r] = kv.x; KPs[d0 + 1][r] = kv.y;
                KPs[d0 + 2][r] = kv.z; KPs[d0 + 3][r] = kv.w;
                float4 vv = *reinterpret_cast<const float4*>(
                    &Vg[(size_t)(kt * 64 + r) * HH + d0]);
                *reinterpret_cast<float4*>(&Vs[r][d0]) = vv;
            }
        }
        __syncthreads();

        float s[4][4];
#pragma unroll
        for (int i = 0; i < 4; i++)
#pragma unroll
            for (int j = 0; j < 4; j++) s[i][j] = 0.f;

#pragma unroll 8
        for (int d = 0; d < 64; d++) {
            float4 a  = *reinterpret_cast<const float4*>(&Qs[d][(ty << 2)]);
            float4 bf = *reinterpret_cast<const float4*>(&KPs[d][(tx << 2)]);
            float av[4] = {a.x, a.y, a.z, a.w};
            float bv[4] = {bf.x, bf.y, bf.z, bf.w};
#pragma unroll
            for (int i = 0; i < 4; i++)
#pragma unroll
                for (int j = 0; j < 4; j++) s[i][j] += av[i] * bv[j];
        }

        const int colbase = kt * 64 + (tx << 2);
#pragma unroll
        for (int i = 0; i < 4; i++) {
            int qr = (ty << 2) + i;
            float4 rv = *reinterpret_cast<const float4*>(
                &relb[(size_t)qr * LL + colbase]);
            float rvv[4] = {rv.x, rv.y, rv.z, rv.w};
#pragma unroll
            for (int j = 0; j < 4; j++) {
                s[i][j] = s[i][j] * 0.125f + rvv[j];
                if (colbase + j >= len) s[i][j] = -1e30f;
            }
        }

#pragma unroll
        for (int i = 0; i < 4; i++) {
            float mx = fmaxf(fmaxf(s[i][0], s[i][1]), fmaxf(s[i][2], s[i][3]));
#pragma unroll
            for (int off = 8; off > 0; off >>= 1)
                mx = fmaxf(mx, __shfl_xor_sync(0xffffffffu, mx, off));
            float mnew = fmaxf(m_i[i], mx);
            float corr = __expf(m_i[i] - mnew);
            m_i[i] = mnew;
            float sum = 0.f;
#pragma unroll
            for (int j = 0; j < 4; j++) {
                s[i][j] = __expf(s[i][j] - mnew);
                sum += s[i][j];
            }
#pragma unroll
            for (int off = 8; off > 0; off >>= 1)
                sum += __shfl_xor_sync(0xffffffffu, sum, off);
            l_i[i] = l_i[i] * corr + sum;
#pragma unroll
            for (int j = 0; j < 4; j++) o[i][j] *= corr;
        }

        __syncthreads();
#pragma unroll
        for (int i = 0; i < 4; i++)
#pragma unroll
            for (int j = 0; j < 4; j++)
                KPs[(tx << 2) + j][(ty << 2) + i] = s[i][j];
        __syncthreads();

#pragma unroll 8
        for (int kk = 0; kk < 64; kk++) {
            float4 a  = *reinterpret_cast<const float4*>(&KPs[kk][(ty << 2)]);
            float4 bf = *reinterpret_cast<const float4*>(&Vs[kk][(tx << 2)]);
            float av[4] = {a.x, a.y, a.z, a.w};
            float bv[4] = {bf.x, bf.y, bf.z, bf.w};
#pragma unroll
            for (int i = 0; i < 4; i++)
#pragma unroll
                for (int j = 0; j < 4; j++) o[i][j] += av[i] * bv[j];
        }
    }

    float* Og = g_att + (size_t)b * (LL * HH) + (size_t)h * DD;
#pragma unroll
    for (int i = 0; i < 4; i++) {
        float inv = 1.0f / l_i[i];
        float4 ov;
        ov.x = o[i][0] * inv; ov.y = o[i][1] * inv;
        ov.z = o[i][2] * inv; ov.w = o[i][3] * inv;
        *reinterpret_cast<float4*>(
            &Og[(size_t)(qt * 64 + (ty << 2) + i) * HH + (tx << 2)]) = ov;
    }
}

// ---------------------------------------------------------------------------
extern "C" void kernel_launch(void* const* d_in, const int* in_sizes, int n_in,
                              void* d_out, int out_size)
{
    const float* key   = (const float*)d_in[0];
    const float* query = (const float*)d_in[1];
    const float* value = (const float*)d_in[2];
    const float* rel   = (const float*)d_in[3];
    const float* wk_w  = (const float*)d_in[4];
    const float* wk_b  = (const float*)d_in[5];
    const float* wq_w  = (const float*)d_in[6];
    const float* wq_b  = (const float*)d_in[7];
    const float* wv_w  = (const float*)d_in[8];
    const float* wv_b  = (const float*)d_in[9];
    const float* ff_w  = (const float*)d_in[10];
    const float* ff_b  = (const float*)d_in[11];
    const int* seq_len = (const int*)d_in[12];
    const int* lex_num = (const int*)d_in[13];
    float* out = (float*)d_out;

    cudaFuncSetAttribute(proj3_mma_kernel,
                         cudaFuncAttributeMaxDynamicSharedMemorySize, DYN_SMEM);
    cudaFuncSetAttribute(ff_mma_kernel,
                         cudaFuncAttributeMaxDynamicSharedMemorySize, DYN_SMEM);

    // Q/K/V projections via tf32 mma.sync (z selects which)
    proj3_mma_kernel<<<dim3(4, 32, 3), 256, DYN_SMEM>>>(query, key, value,
                                                        wq_w, wq_b, wk_w, wk_b,
                                                        wv_w, wv_b);
    // fused attention (rel bias + mask + softmax + PV) — fp32 SIMT
    attn_kernel<<<dim3(16, NHEAD, BB), 256>>>(rel, seq_len, lex_num);
    // output projection via tf32 mma.sync
    ff_mma_kernel<<<dim3(4, 32), 256, DYN_SMEM>>>(ff_w, ff_b, out);
}

// round 5
// speedup vs baseline: 2.6393x; 1.7604x over previous
#include <cuda_runtime.h>
#include <math.h>
#include <stdint.h>

// Problem constants
#define BB 4
#define LL 1024
#define HH 512
#define NHEAD 8
#define DD 64

// Scratch (device globals — no allocation allowed)
__device__ float g_q[BB * LL * HH];
__device__ float g_k[BB * LL * HH];
__device__ float g_v[BB * LL * HH];
__device__ float g_att[BB * LL * HH];

// ===========================================================================
// Helpers
// ===========================================================================
__device__ __forceinline__ uint32_t smem_u32(const void* p) {
    return (uint32_t)__cvta_generic_to_shared(p);
}
__device__ __forceinline__ void cp_async16(uint32_t dst, const void* src) {
    asm volatile("cp.async.cg.shared.global [%0], [%1], 16;"
                 :: "r"(dst), "l"(src) : "memory");
}
#define CP_COMMIT() asm volatile("cp.async.commit_group;" ::: "memory")

__device__ __forceinline__ uint32_t f2tf32(float x) {
    uint32_t r;
    asm("cvt.rna.tf32.f32 %0, %1;" : "=r"(r) : "f"(x));
    return r;
}
__device__ __forceinline__ void mma_tf32(float* d, const uint32_t* a, const uint32_t* b) {
    asm volatile(
        "mma.sync.aligned.m16n8k8.row.col.f32.tf32.tf32.f32 "
        "{%0,%1,%2,%3}, {%4,%5,%6,%7}, {%8,%9}, {%0,%1,%2,%3};"
        : "+f"(d[0]), "+f"(d[1]), "+f"(d[2]), "+f"(d[3])
        : "r"(a[0]), "r"(a[1]), "r"(a[2]), "r"(a[3]), "r"(b[0]), "r"(b[1]));
}

// ===========================================================================
// tf32 mma.sync GEMM:  Y[M,512] = X[M,512] @ W[512,512]^T + bias
// (UNCHANGED from round-4 passing version)
// ===========================================================================
#define BK 32
#define PITCH 36
#define STAGE_F (128 * PITCH)          // floats per operand per stage
#define DYN_SMEM (4 * STAGE_F * 4)     // 2 ops x 2 stages = 73728 B

__device__ __forceinline__ void gemm_mma_body(
    const float* __restrict__ X, const float* __restrict__ W,
    const float* __restrict__ bias, float* __restrict__ Y,
    int bx, int by)
{
    extern __shared__ float sm[];
    float* As[2] = { sm,               sm + STAGE_F };
    float* Bs[2] = { sm + 2 * STAGE_F, sm + 3 * STAGE_F };

    const int tid  = threadIdx.x;
    const int w    = tid >> 5;
    const int lane = tid & 31;
    const int lr   = lane >> 2;        // 0..7
    const int lc   = lane & 3;         // 0..3
    const int wm   = (w >> 2) * 64;    // warp m offset
    const int wn   = (w & 3) * 32;     // warp n offset
    const int row0 = by * 128;
    const int col0 = bx * 128;

    float acc[4][4][4];
#pragma unroll
    for (int i = 0; i < 4; i++)
#pragma unroll
        for (int j = 0; j < 4; j++)
#pragma unroll
            for (int t = 0; t < 4; t++) acc[i][j][t] = 0.f;

#define LOAD_STAGE(IT)                                                        \
    do {                                                                      \
        const int s_  = (IT) & 1;                                             \
        const int k0_ = (IT) * BK;                                            \
        _Pragma("unroll")                                                     \
        for (int p = 0; p < 4; p++) {                                         \
            int id = tid + (p << 8);                                          \
            int r = id >> 3, c = id & 7;                                      \
            cp_async16(smem_u32(&As[s_][r * PITCH + c * 4]),                  \
                       &X[(size_t)(row0 + r) * 512 + k0_ + c * 4]);           \
        }                                                                     \
        _Pragma("unroll")                                                     \
        for (int p = 0; p < 4; p++) {                                         \
            int id = tid + (p << 8);                                          \
            int r = id >> 3, c = id & 7;                                      \
            cp_async16(smem_u32(&Bs[s_][r * PITCH + c * 4]),                  \
                       &W[(size_t)(col0 + r) * 512 + k0_ + c * 4]);           \
        }                                                                     \
        CP_COMMIT();                                                          \
    } while (0)

    LOAD_STAGE(0);

    for (int it = 0; it < 16; it++) {
        if (it + 1 < 16) {
            LOAD_STAGE(it + 1);
            asm volatile("cp.async.wait_group 1;" ::: "memory");
        } else {
            asm volatile("cp.async.wait_group 0;" ::: "memory");
        }
        __syncthreads();

        const float* A = As[it & 1];
        const float* B = Bs[it & 1];
#pragma unroll
        for (int kk = 0; kk < BK; kk += 8) {
            uint32_t a[4][4], b[4][2];
#pragma unroll
            for (int i = 0; i < 4; i++) {
                const float* ap = &A[(wm + i * 16 + lr) * PITCH + kk + lc];
                a[i][0] = f2tf32(ap[0]);
                a[i][1] = f2tf32(ap[8 * PITCH]);
                a[i][2] = f2tf32(ap[4]);
                a[i][3] = f2tf32(ap[8 * PITCH + 4]);
            }
#pragma unroll
            for (int j = 0; j < 4; j++) {
                const float* bp = &B[(wn + j * 8 + lr) * PITCH + kk + lc];
                b[j][0] = f2tf32(bp[0]);
                b[j][1] = f2tf32(bp[4]);
            }
#pragma unroll
            for (int i = 0; i < 4; i++)
#pragma unroll
                for (int j = 0; j < 4; j++)
                    mma_tf32(acc[i][j], a[i], b[j]);
        }
        __syncthreads();
    }

#pragma unroll
    for (int j = 0; j < 4; j++) {
        const int col = col0 + wn + j * 8 + lc * 2;
        const float2 bb = *reinterpret_cast<const float2*>(&bias[col]);
#pragma unroll
        for (int i = 0; i < 4; i++) {
            const int r0 = row0 + wm + i * 16 + lr;
            float2 o0 = { acc[i][j][0] + bb.x, acc[i][j][1] + bb.y };
            float2 o1 = { acc[i][j][2] + bb.x, acc[i][j][3] + bb.y };
            *reinterpret_cast<float2*>(&Y[(size_t)r0 * 512 + col]) = o0;
            *reinterpret_cast<float2*>(&Y[(size_t)(r0 + 8) * 512 + col]) = o1;
        }
    }
#undef LOAD_STAGE
}

__global__ __launch_bounds__(256, 1)
void proj3_mma_kernel(const float* __restrict__ q_in, const float* __restrict__ k_in,
                      const float* __restrict__ v_in,
                      const float* __restrict__ wq, const float* __restrict__ bq,
                      const float* __restrict__ wk, const float* __restrict__ bk,
                      const float* __restrict__ wv, const float* __restrict__ bv)
{
    const float* X; const float* W; const float* bias; float* Y;
    if (blockIdx.z == 0)      { X = q_in; W = wq; bias = bq; Y = g_q; }
    else if (blockIdx.z == 1) { X = k_in; W = wk; bias = bk; Y = g_k; }
    else                      { X = v_in; W = wv; bias = bv; Y = g_v; }
    gemm_mma_body(X, W, bias, Y, blockIdx.x, blockIdx.y);
}

__global__ __launch_bounds__(256, 1)
void ff_mma_kernel(const float* __restrict__ w, const float* __restrict__ bias,
                   float* __restrict__ out)
{
    gemm_mma_body(g_att, w, bias, out, blockIdx.x, blockIdx.y);
}

// ===========================================================================
// Tensor-core fused attention. CTA = 64 q-rows x (b,h). 4 warps, each owns
// 16 q-rows -> warp-private softmax (4-lane shfl row reduce). K/V tiles
// double-buffered via cp.async; P kept warp-private in smem as tf32 bits.
// Masked key tiles skipped entirely.
// ===========================================================================
#define KPITCH 68   // bank: 4*lr+lc  -> conflict-free B/A frag reads
#define VPITCH 72   // bank: 8*lc+lr  -> conflict-free B frag reads
#define KS_F (64 * KPITCH)
#define VS_F (64 * VPITCH)
#define ATT_SMEM ((2 * KS_F + 2 * VS_F + 64 * KPITCH) * 4)   // 89088 B

__global__ __launch_bounds__(128, 2)
void attn_mma_kernel(const float* __restrict__ rel,
                     const int* __restrict__ seq_len,
                     const int* __restrict__ lex_num)
{
    extern __shared__ float asmem[];
    float* Ks = asmem;                       // [2][64][KPITCH]
    float* Vs = asmem + 2 * KS_F;            // [2][64][VPITCH]
    uint32_t* Ps = (uint32_t*)(asmem + 2 * KS_F + 2 * VS_F);  // [64][KPITCH] tf32

    const int qt = blockIdx.x;
    const int h  = blockIdx.y;
    const int b  = blockIdx.z;
    const int tid  = threadIdx.x;
    const int w    = tid >> 5;
    const int lane = tid & 31;
    const int lr   = lane >> 2;       // 0..7
    const int lc   = lane & 3;        // 0..3

    const int len = seq_len[b] + lex_num[b];
    int ntiles = (len + 63) >> 6;
    if (ntiles > 16) ntiles = 16;

    const float* Qg   = g_q + ((size_t)b * LL + qt * 64) * HH + h * DD;
    const float* Kg   = g_k + (size_t)b * LL * HH + h * DD;
    const float* Vg   = g_v + (size_t)b * LL * HH + h * DD;
    const float* relb = rel + (((size_t)b * NHEAD + h) * LL + (size_t)qt * 64) * LL;

    const int r0 = w * 16 + lr;       // this thread's first q-row (local)

    // Q fragments, converted to tf32 once (A-frag layout for m16n8k8)
    uint32_t qf[8][4];
#pragma unroll
    for (int kk = 0; kk < 8; kk++) {
        qf[kk][0] = f2tf32(Qg[(size_t)r0 * HH + kk * 8 + lc]);
        qf[kk][1] = f2tf32(Qg[(size_t)(r0 + 8) * HH + kk * 8 + lc]);
        qf[kk][2] = f2tf32(Qg[(size_t)r0 * HH + kk * 8 + lc + 4]);
        qf[kk][3] = f2tf32(Qg[(size_t)(r0 + 8) * HH + kk * 8 + lc + 4]);
    }

    float m_i[2] = { -1e30f, -1e30f };
    float l_i[2] = { 0.f, 0.f };
    float oacc[8][4];
#pragma unroll
    for (int j = 0; j < 8; j++)
#pragma unroll
        for (int t = 0; t < 4; t++) oacc[j][t] = 0.f;

#define ATT_LOAD(KT)                                                          \
    do {                                                                      \
        const int s_ = (KT) & 1;                                              \
        const float* ksrc = Kg + (size_t)(KT) * 64 * HH;                      \
        const float* vsrc = Vg + (size_t)(KT) * 64 * HH;                      \
        float* kd = Ks + s_ * KS_F;                                           \
        float* vd = Vs + s_ * VS_F;                                           \
        _Pragma("unroll")                                                     \
        for (int p = 0; p < 8; p++) {                                         \
            int id = tid + (p << 7);                                          \
            int r = id >> 4, c = id & 15;                                     \
            cp_async16(smem_u32(kd + r * KPITCH + c * 4),                     \
                       ksrc + (size_t)r * HH + c * 4);                        \
            cp_async16(smem_u32(vd + r * VPITCH + c * 4),                     \
                       vsrc + (size_t)r * HH + c * 4);                        \
        }                                                                     \
        CP_COMMIT();                                                          \
    } while (0)

    ATT_LOAD(0);

    for (int kt = 0; kt < ntiles; kt++) {
        asm volatile("cp.async.wait_group 0;" ::: "memory");
        __syncthreads();                          // tile kt visible; prev buffer free
        if (kt + 1 < ntiles) ATT_LOAD(kt + 1);    // overlap next load with compute

        const float* K0 = Ks + (kt & 1) * KS_F;
        const float* V0 = Vs + (kt & 1) * VS_F;

        // ---- S = Q @ K^T  (warp: 16 x 64, k=64)
        float sacc[8][4];
#pragma unroll
        for (int j = 0; j < 8; j++)
#pragma unroll
            for (int t = 0; t < 4; t++) sacc[j][t] = 0.f;

#pragma unroll
        for (int kk = 0; kk < 8; kk++) {
#pragma unroll
            for (int j = 0; j < 8; j++) {
                uint32_t bb[2];
                const float* kp = &K0[(j * 8 + lr) * KPITCH + kk * 8 + lc];
                bb[0] = f2tf32(kp[0]);
                bb[1] = f2tf32(kp[4]);
                mma_tf32(sacc[j], qf[kk], bb);
            }
        }

        // ---- rel bias + scale + padding mask
        const int colbase = kt * 64;
        float2 rl0[8], rl1[8];
#pragma unroll
        for (int j = 0; j < 8; j++) {
            rl0[j] = *reinterpret_cast<const float2*>(
                &relb[(size_t)r0 * LL + colbase + j * 8 + 2 * lc]);
            rl1[j] = *reinterpret_cast<const float2*>(
                &relb[(size_t)(r0 + 8) * LL + colbase + j * 8 + 2 * lc]);
        }
#pragma unroll
        for (int j = 0; j < 8; j++) {
            const int c0 = colbase + j * 8 + 2 * lc;
            sacc[j][0] = (c0     < len) ? sacc[j][0] * 0.125f + rl0[j].x : -1e30f;
            sacc[j][1] = (c0 + 1 < len) ? sacc[j][1] * 0.125f + rl0[j].y : -1e30f;
            sacc[j][2] = (c0     < len) ? sacc[j][2] * 0.125f + rl1[j].x : -1e30f;
            sacc[j][3] = (c0 + 1 < len) ? sacc[j][3] * 0.125f + rl1[j].y : -1e30f;
        }

        // ---- online softmax (two rows per thread; reduce over 4 lanes)
#pragma unroll
        for (int t = 0; t < 2; t++) {
            float mx = -1e30f;
#pragma unroll
            for (int j = 0; j < 8; j++)
                mx = fmaxf(mx, fmaxf(sacc[j][2 * t], sacc[j][2 * t + 1]));
            mx = fmaxf(mx, __shfl_xor_sync(0xffffffffu, mx, 1));
            mx = fmaxf(mx, __shfl_xor_sync(0xffffffffu, mx, 2));
            const float mnew = fmaxf(m_i[t], mx);
            const float corr = __expf(m_i[t] - mnew);
            m_i[t] = mnew;
            float sum = 0.f;
#pragma unroll
            for (int j = 0; j < 8; j++) {
                sacc[j][2 * t]     = __expf(sacc[j][2 * t] - mnew);
                sacc[j][2 * t + 1] = __expf(sacc[j][2 * t + 1] - mnew);
                sum += sacc[j][2 * t] + sacc[j][2 * t + 1];
            }
            sum += __shfl_xor_sync(0xffffffffu, sum, 1);
            sum += __shfl_xor_sync(0xffffffffu, sum, 2);
            l_i[t] = l_i[t] * corr + sum;
#pragma unroll
            for (int j = 0; j < 8; j++) {
                oacc[j][2 * t]     *= corr;
                oacc[j][2 * t + 1] *= corr;
            }
        }

        // ---- P to warp-private smem slice (as tf32 bits)
#pragma unroll
        for (int j = 0; j < 8; j++) {
            uint32_t* p0 = Ps + (size_t)r0 * KPITCH + j * 8 + 2 * lc;
            uint32_t* p1 = Ps + (size_t)(r0 + 8) * KPITCH + j * 8 + 2 * lc;
            p0[0] = f2tf32(sacc[j][0]); p0[1] = f2tf32(sacc[j][1]);
            p1[0] = f2tf32(sacc[j][2]); p1[1] = f2tf32(sacc[j][3]);
        }
        __syncwarp();

        // ---- O += P @ V  (warp: 16 x 64, k=64)
#pragma unroll
        for (int kk = 0; kk < 8; kk++) {
            uint32_t af[4];
            af[0] = Ps[(size_t)r0 * KPITCH + kk * 8 + lc];
            af[1] = Ps[(size_t)(r0 + 8) * KPITCH + kk * 8 + lc];
            af[2] = Ps[(size_t)r0 * KPITCH + kk * 8 + lc + 4];
            af[3] = Ps[(size_t)(r0 + 8) * KPITCH + kk * 8 + lc + 4];
#pragma unroll
            for (int j = 0; j < 8; j++) {
                uint32_t bb[2];
                bb[0] = f2tf32(V0[(kk * 8 + lc) * VPITCH + j * 8 + lr]);
                bb[1] = f2tf32(V0[(kk * 8 + lc + 4) * VPITCH + j * 8 + lr]);
                mma_tf32(oacc[j], af, bb);
            }
        }
        __syncwarp();   // Ps reads done before next iteration overwrites
    }

    // ---- normalize + store
    float* Og = g_att + ((size_t)b * LL + qt * 64) * HH + h * DD;
    const float inv0 = 1.0f / l_i[0];
    const float inv1 = 1.0f / l_i[1];
#pragma unroll
    for (int j = 0; j < 8; j++) {
        float2 o0 = { oacc[j][0] * inv0, oacc[j][1] * inv0 };
        float2 o1 = { oacc[j][2] * inv1, oacc[j][3] * inv1 };
        *reinterpret_cast<float2*>(&Og[(size_t)r0 * HH + j * 8 + 2 * lc]) = o0;
        *reinterpret_cast<float2*>(&Og[(size_t)(r0 + 8) * HH + j * 8 + 2 * lc]) = o1;
    }
#undef ATT_LOAD
}

// ---------------------------------------------------------------------------
extern "C" void kernel_launch(void* const* d_in, const int* in_sizes, int n_in,
                              void* d_out, int out_size)
{
    const float* key   = (const float*)d_in[0];
    const float* query = (const float*)d_in[1];
    const float* value = (const float*)d_in[2];
    const float* rel   = (const float*)d_in[3];
    const float* wk_w  = (const float*)d_in[4];
    const float* wk_b  = (const float*)d_in[5];
    const float* wq_w  = (const float*)d_in[6];
    const float* wq_b  = (const float*)d_in[7];
    const float* wv_w  = (const float*)d_in[8];
    const float* wv_b  = (const float*)d_in[9];
    const float* ff_w  = (const float*)d_in[10];
    const float* ff_b  = (const float*)d_in[11];
    const int* seq_len = (const int*)d_in[12];
    const int* lex_num = (const int*)d_in[13];
    float* out = (float*)d_out;

    cudaFuncSetAttribute(proj3_mma_kernel,
                         cudaFuncAttributeMaxDynamicSharedMemorySize, DYN_SMEM);
    cudaFuncSetAttribute(ff_mma_kernel,
                         cudaFuncAttributeMaxDynamicSharedMemorySize, DYN_SMEM);
    cudaFuncSetAttribute(attn_mma_kernel,
                         cudaFuncAttributeMaxDynamicSharedMemorySize, ATT_SMEM);

    proj3_mma_kernel<<<dim3(4, 32, 3), 256, DYN_SMEM>>>(query, key, value,
                                                        wq_w, wq_b, wk_w, wk_b,
                                                        wv_w, wv_b);
    attn_mma_kernel<<<dim3(16, NHEAD, BB), 128, ATT_SMEM>>>(rel, seq_len, lex_num);
    ff_mma_kernel<<<dim3(4, 32), 256, DYN_SMEM>>>(ff_w, ff_b, out);
}

// round 6
// speedup vs baseline: 2.7320x; 1.0351x over previous
#include <cuda_runtime.h>
#include <math.h>
#include <stdint.h>

// Problem constants
#define BB 4
#define LL 1024
#define HH 512
#define NHEAD 8
#define DD 64

// Scratch (device globals — no allocation allowed)
__device__ float g_q[BB * LL * HH];
__device__ float g_k[BB * LL * HH];
__device__ float g_v[BB * LL * HH];
__device__ float g_att[BB * LL * HH];

// ===========================================================================
// Helpers
// ===========================================================================
__device__ __forceinline__ uint32_t smem_u32(const void* p) {
    return (uint32_t)__cvta_generic_to_shared(p);
}
__device__ __forceinline__ void cp_async16(uint32_t dst, const void* src) {
    asm volatile("cp.async.cg.shared.global [%0], [%1], 16;"
                 :: "r"(dst), "l"(src) : "memory");
}
#define CP_COMMIT() asm volatile("cp.async.commit_group;" ::: "memory")

__device__ __forceinline__ uint32_t f2tf32(float x) {
    uint32_t r;
    asm("cvt.rna.tf32.f32 %0, %1;" : "=r"(r) : "f"(x));
    return r;
}
__device__ __forceinline__ void mma_tf32(float* d, const uint32_t* a, const uint32_t* b) {
    asm volatile(
        "mma.sync.aligned.m16n8k8.row.col.f32.tf32.tf32.f32 "
        "{%0,%1,%2,%3}, {%4,%5,%6,%7}, {%8,%9}, {%0,%1,%2,%3};"
        : "+f"(d[0]), "+f"(d[1]), "+f"(d[2]), "+f"(d[3])
        : "r"(a[0]), "r"(a[1]), "r"(a[2]), "r"(a[3]), "r"(b[0]), "r"(b[1]));
}

// ===========================================================================
// tf32 mma.sync GEMM:  Y[M,512] = X[M,512] @ W[512,512]^T + bias
// CTA tile 64x128 (3 CTAs/SM -> 24 warps), 8 warps (2x4), warp tile 32x32,
// BK=32, double-buffered cp.async. Smem pitch 36 -> conflict-free frag LDS.
// ===========================================================================
#define BK 32
#define PITCH 36
#define A_STAGE (64 * PITCH)                       // floats per A stage
#define B_STAGE (128 * PITCH)                      // floats per B stage
#define DYN_SMEM ((2 * A_STAGE + 2 * B_STAGE) * 4) // 55296 B

__device__ __forceinline__ void gemm_mma_body(
    const float* __restrict__ X, const float* __restrict__ W,
    const float* __restrict__ bias, float* __restrict__ Y,
    int bx, int by)
{
    extern __shared__ float sm[];
    float* As[2] = { sm,               sm + A_STAGE };
    float* Bs[2] = { sm + 2 * A_STAGE, sm + 2 * A_STAGE + B_STAGE };

    const int tid  = threadIdx.x;
    const int w    = tid >> 5;
    const int lane = tid & 31;
    const int lr   = lane >> 2;        // 0..7
    const int lc   = lane & 3;         // 0..3
    const int wm   = (w >> 2) * 32;    // warp m offset (0/32)
    const int wn   = (w & 3) * 32;     // warp n offset (0..96)
    const int row0 = by * 64;
    const int col0 = bx * 128;

    float acc[2][4][4];
#pragma unroll
    for (int i = 0; i < 2; i++)
#pragma unroll
        for (int j = 0; j < 4; j++)
#pragma unroll
            for (int t = 0; t < 4; t++) acc[i][j][t] = 0.f;

    // ---- stage loader: A = 64x32 (512 f4), B = 128x32 (1024 f4)
#define LOAD_STAGE(IT)                                                        \
    do {                                                                      \
        const int s_  = (IT) & 1;                                             \
        const int k0_ = (IT) * BK;                                            \
        _Pragma("unroll")                                                     \
        for (int p = 0; p < 2; p++) {                                         \
            int id = tid + (p << 8);                                          \
            int r = id >> 3, c = id & 7;                                      \
            cp_async16(smem_u32(&As[s_][r * PITCH + c * 4]),                  \
                       &X[(size_t)(row0 + r) * 512 + k0_ + c * 4]);           \
        }                                                                     \
        _Pragma("unroll")                                                     \
        for (int p = 0; p < 4; p++) {                                         \
            int id = tid + (p << 8);                                          \
            int r = id >> 3, c = id & 7;                                      \
            cp_async16(smem_u32(&Bs[s_][r * PITCH + c * 4]),                  \
                       &W[(size_t)(col0 + r) * 512 + k0_ + c * 4]);           \
        }                                                                     \
        CP_COMMIT();                                                          \
    } while (0)

    LOAD_STAGE(0);

    for (int it = 0; it < 16; it++) {
        if (it + 1 < 16) {
            LOAD_STAGE(it + 1);
            asm volatile("cp.async.wait_group 1;" ::: "memory");
        } else {
            asm volatile("cp.async.wait_group 0;" ::: "memory");
        }
        __syncthreads();

        const float* A = As[it & 1];
        const float* B = Bs[it & 1];
#pragma unroll
        for (int kk = 0; kk < BK; kk += 8) {
            uint32_t a[2][4];
#pragma unroll
            for (int i = 0; i < 2; i++) {
                const float* ap = &A[(wm + i * 16 + lr) * PITCH + kk + lc];
                a[i][0] = f2tf32(ap[0]);
                a[i][1] = f2tf32(ap[8 * PITCH]);
                a[i][2] = f2tf32(ap[4]);
                a[i][3] = f2tf32(ap[8 * PITCH + 4]);
            }
#pragma unroll
            for (int j = 0; j < 4; j++) {
                const float* bp = &B[(wn + j * 8 + lr) * PITCH + kk + lc];
                uint32_t bb[2];
                bb[0] = f2tf32(bp[0]);
                bb[1] = f2tf32(bp[4]);
                mma_tf32(acc[0][j], a[0], bb);
                mma_tf32(acc[1][j], a[1], bb);
            }
        }
        __syncthreads();
    }

    // ---- epilogue: +bias, float2 stores
#pragma unroll
    for (int j = 0; j < 4; j++) {
        const int col = col0 + wn + j * 8 + lc * 2;
        const float2 bb = *reinterpret_cast<const float2*>(&bias[col]);
#pragma unroll
        for (int i = 0; i < 2; i++) {
            const int r0 = row0 + wm + i * 16 + lr;
            float2 o0 = { acc[i][j][0] + bb.x, acc[i][j][1] + bb.y };
            float2 o1 = { acc[i][j][2] + bb.x, acc[i][j][3] + bb.y };
            *reinterpret_cast<float2*>(&Y[(size_t)r0 * 512 + col]) = o0;
            *reinterpret_cast<float2*>(&Y[(size_t)(r0 + 8) * 512 + col]) = o1;
        }
    }
#undef LOAD_STAGE
}

__global__ __launch_bounds__(256, 3)
void proj3_mma_kernel(const float* __restrict__ q_in, const float* __restrict__ k_in,
                      const float* __restrict__ v_in,
                      const float* __restrict__ wq, const float* __restrict__ bq,
                      const float* __restrict__ wk, const float* __restrict__ bk,
                      const float* __restrict__ wv, const float* __restrict__ bv)
{
    const float* X; const float* W; const float* bias; float* Y;
    if (blockIdx.z == 0)      { X = q_in; W = wq; bias = bq; Y = g_q; }
    else if (blockIdx.z == 1) { X = k_in; W = wk; bias = bk; Y = g_k; }
    else                      { X = v_in; W = wv; bias = bv; Y = g_v; }
    gemm_mma_body(X, W, bias, Y, blockIdx.x, blockIdx.y);
}

__global__ __launch_bounds__(256, 3)
void ff_mma_kernel(const float* __restrict__ w, const float* __restrict__ bias,
                   float* __restrict__ out)
{
    gemm_mma_body(g_att, w, bias, out, blockIdx.x, blockIdx.y);
}

// ===========================================================================
// Tensor-core fused attention (UNCHANGED from round-5 passing version).
// CTA = 64 q-rows x (b,h). 4 warps, each owns 16 q-rows -> warp-private
// softmax. K/V double-buffered cp.async; P as tf32 bits in warp-private smem.
// Masked key tiles skipped entirely.
// ===========================================================================
#define KPITCH 68   // bank: 4*lr+lc  -> conflict-free B/A frag reads
#define VPITCH 72   // bank: 8*lc+lr  -> conflict-free B frag reads
#define KS_F (64 * KPITCH)
#define VS_F (64 * VPITCH)
#define ATT_SMEM ((2 * KS_F + 2 * VS_F + 64 * KPITCH) * 4)   // 89088 B

__global__ __launch_bounds__(128, 2)
void attn_mma_kernel(const float* __restrict__ rel,
                     const int* __restrict__ seq_len,
                     const int* __restrict__ lex_num)
{
    extern __shared__ float asmem[];
    float* Ks = asmem;                       // [2][64][KPITCH]
    float* Vs = asmem + 2 * KS_F;            // [2][64][VPITCH]
    uint32_t* Ps = (uint32_t*)(asmem + 2 * KS_F + 2 * VS_F);  // [64][KPITCH] tf32

    const int qt = blockIdx.x;
    const int h  = blockIdx.y;
    const int b  = blockIdx.z;
    const int tid  = threadIdx.x;
    const int w    = tid >> 5;
    const int lane = tid & 31;
    const int lr   = lane >> 2;       // 0..7
    const int lc   = lane & 3;        // 0..3

    const int len = seq_len[b] + lex_num[b];
    int ntiles = (len + 63) >> 6;
    if (ntiles > 16) ntiles = 16;

    const float* Qg   = g_q + ((size_t)b * LL + qt * 64) * HH + h * DD;
    const float* Kg   = g_k + (size_t)b * LL * HH + h * DD;
    const float* Vg   = g_v + (size_t)b * LL * HH + h * DD;
    const float* relb = rel + (((size_t)b * NHEAD + h) * LL + (size_t)qt * 64) * LL;

    const int r0 = w * 16 + lr;       // this thread's first q-row (local)

    // Q fragments, converted to tf32 once (A-frag layout for m16n8k8)
    uint32_t qf[8][4];
#pragma unroll
    for (int kk = 0; kk < 8; kk++) {
        qf[kk][0] = f2tf32(Qg[(size_t)r0 * HH + kk * 8 + lc]);
        qf[kk][1] = f2tf32(Qg[(size_t)(r0 + 8) * HH + kk * 8 + lc]);
        qf[kk][2] = f2tf32(Qg[(size_t)r0 * HH + kk * 8 + lc + 4]);
        qf[kk][3] = f2tf32(Qg[(size_t)(r0 + 8) * HH + kk * 8 + lc + 4]);
    }

    float m_i[2] = { -1e30f, -1e30f };
    float l_i[2] = { 0.f, 0.f };
    float oacc[8][4];
#pragma unroll
    for (int j = 0; j < 8; j++)
#pragma unroll
        for (int t = 0; t < 4; t++) oacc[j][t] = 0.f;

#define ATT_LOAD(KT)                                                          \
    do {                                                                      \
        const int s_ = (KT) & 1;                                              \
        const float* ksrc = Kg + (size_t)(KT) * 64 * HH;                      \
        const float* vsrc = Vg + (size_t)(KT) * 64 * HH;                      \
        float* kd = Ks + s_ * KS_F;                                           \
        float* vd = Vs + s_ * VS_F;                                           \
        _Pragma("unroll")                                                     \
        for (int p = 0; p < 8; p++) {                                         \
            int id = tid + (p << 7);                                          \
            int r = id >> 4, c = id & 15;                                     \
            cp_async16(smem_u32(kd + r * KPITCH + c * 4),                     \
                       ksrc + (size_t)r * HH + c * 4);                        \
            cp_async16(smem_u32(vd + r * VPITCH + c * 4),                     \
                       vsrc + (size_t)r * HH + c * 4);                        \
        }                                                                     \
        CP_COMMIT();                                                          \
    } while (0)

    ATT_LOAD(0);

    for (int kt = 0; kt < ntiles; kt++) {
        asm volatile("cp.async.wait_group 0;" ::: "memory");
        __syncthreads();                          // tile kt visible; prev buffer free
        if (kt + 1 < ntiles) ATT_LOAD(kt + 1);    // overlap next load with compute

        const float* K0 = Ks + (kt & 1) * KS_F;
        const float* V0 = Vs + (kt & 1) * VS_F;

        // ---- S = Q @ K^T  (warp: 16 x 64, k=64)
        float sacc[8][4];
#pragma unroll
        for (int j = 0; j < 8; j++)
#pragma unroll
            for (int t = 0; t < 4; t++) sacc[j][t] = 0.f;

#pragma unroll
        for (int kk = 0; kk < 8; kk++) {
#pragma unroll
            for (int j = 0; j < 8; j++) {
                uint32_t bb[2];
                const float* kp = &K0[(j * 8 + lr) * KPITCH + kk * 8 + lc];
                bb[0] = f2tf32(kp[0]);
                bb[1] = f2tf32(kp[4]);
                mma_tf32(sacc[j], qf[kk], bb);
            }
        }

        // ---- rel bias + scale + padding mask
        const int colbase = kt * 64;
        float2 rl0[8], rl1[8];
#pragma unroll
        for (int j = 0; j < 8; j++) {
            rl0[j] = *reinterpret_cast<const float2*>(
                &relb[(size_t)r0 * LL + colbase + j * 8 + 2 * lc]);
            rl1[j] = *reinterpret_cast<const float2*>(
                &relb[(size_t)(r0 + 8) * LL + colbase + j * 8 + 2 * lc]);
        }
#pragma unroll
        for (int j = 0; j < 8; j++) {
            const int c0 = colbase + j * 8 + 2 * lc;
            sacc[j][0] = (c0     < len) ? sacc[j][0] * 0.125f + rl0[j].x : -1e30f;
            sacc[j][1] = (c0 + 1 < len) ? sacc[j][1] * 0.125f + rl0[j].y : -1e30f;
            sacc[j][2] = (c0     < len) ? sacc[j][2] * 0.125f + rl1[j].x : -1e30f;
            sacc[j][3] = (c0 + 1 < len) ? sacc[j][3] * 0.125f + rl1[j].y : -1e30f;
        }

        // ---- online softmax (two rows per thread; reduce over 4 lanes)
#pragma unroll
        for (int t = 0; t < 2; t++) {
            float mx = -1e30f;
#pragma unroll
            for (int j = 0; j < 8; j++)
                mx = fmaxf(mx, fmaxf(sacc[j][2 * t], sacc[j][2 * t + 1]));
            mx = fmaxf(mx, __shfl_xor_sync(0xffffffffu, mx, 1));
            mx = fmaxf(mx, __shfl_xor_sync(0xffffffffu, mx, 2));
            const float mnew = fmaxf(m_i[t], mx);
            const float corr = __expf(m_i[t] - mnew);
            m_i[t] = mnew;
            float sum = 0.f;
#pragma unroll
            for (int j = 0; j < 8; j++) {
                sacc[j][2 * t]     = __expf(sacc[j][2 * t] - mnew);
                sacc[j][2 * t + 1] = __expf(sacc[j][2 * t + 1] - mnew);
                sum += sacc[j][2 * t] + sacc[j][2 * t + 1];
            }
            sum += __shfl_xor_sync(0xffffffffu, sum, 1);
            sum += __shfl_xor_sync(0xffffffffu, sum, 2);
            l_i[t] = l_i[t] * corr + sum;
#pragma unroll
            for (int j = 0; j < 8; j++) {
                oacc[j][2 * t]     *= corr;
                oacc[j][2 * t + 1] *= corr;
            }
        }

        // ---- P to warp-private smem slice (as tf32 bits)
#pragma unroll
        for (int j = 0; j < 8; j++) {
            uint32_t* p0 = Ps + (size_t)r0 * KPITCH + j * 8 + 2 * lc;
            uint32_t* p1 = Ps + (size_t)(r0 + 8) * KPITCH + j * 8 + 2 * lc;
            p0[0] = f2tf32(sacc[j][0]); p0[1] = f2tf32(sacc[j][1]);
            p1[0] = f2tf32(sacc[j][2]); p1[1] = f2tf32(sacc[j][3]);
        }
        __syncwarp();

        // ---- O += P @ V  (warp: 16 x 64, k=64)
#pragma unroll
        for (int kk = 0; kk < 8; kk++) {
            uint32_t af[4];
            af[0] = Ps[(size_t)r0 * KPITCH + kk * 8 + lc];
            af[1] = Ps[(size_t)(r0 + 8) * KPITCH + kk * 8 + lc];
            af[2] = Ps[(size_t)r0 * KPITCH + kk * 8 + lc + 4];
            af[3] = Ps[(size_t)(r0 + 8) * KPITCH + kk * 8 + lc + 4];
#pragma unroll
            for (int j = 0; j < 8; j++) {
                uint32_t bb[2];
                bb[0] = f2tf32(V0[(kk * 8 + lc) * VPITCH + j * 8 + lr]);
                bb[1] = f2tf32(V0[(kk * 8 + lc + 4) * VPITCH + j * 8 + lr]);
                mma_tf32(oacc[j], af, bb);
            }
        }
        __syncwarp();   // Ps reads done before next iteration overwrites
    }

    // ---- normalize + store
    float* Og = g_att + ((size_t)b * LL + qt * 64) * HH + h * DD;
    const float inv0 = 1.0f / l_i[0];
    const float inv1 = 1.0f / l_i[1];
#pragma unroll
    for (int j = 0; j < 8; j++) {
        float2 o0 = { oacc[j][0] * inv0, oacc[j][1] * inv0 };
        float2 o1 = { oacc[j][2] * inv1, oacc[j][3] * inv1 };
        *reinterpret_cast<float2*>(&Og[(size_t)r0 * HH + j * 8 + 2 * lc]) = o0;
        *reinterpret_cast<float2*>(&Og[(size_t)(r0 + 8) * HH + j * 8 + 2 * lc]) = o1;
    }
#undef ATT_LOAD
}

// ---------------------------------------------------------------------------
extern "C" void kernel_launch(void* const* d_in, const int* in_sizes, int n_in,
                              void* d_out, int out_size)
{
    const float* key   = (const float*)d_in[0];
    const float* query = (const float*)d_in[1];
    const float* value = (const float*)d_in[2];
    const float* rel   = (const float*)d_in[3];
    const float* wk_w  = (const float*)d_in[4];
    const float* wk_b  = (const float*)d_in[5];
    const float* wq_w  = (const float*)d_in[6];
    const float* wq_b  = (const float*)d_in[7];
    const float* wv_w  = (const float*)d_in[8];
    const float* wv_b  = (const float*)d_in[9];
    const float* ff_w  = (const float*)d_in[10];
    const float* ff_b  = (const float*)d_in[11];
    const int* seq_len = (const int*)d_in[12];
    const int* lex_num = (const int*)d_in[13];
    float* out = (float*)d_out;

    cudaFuncSetAttribute(proj3_mma_kernel,
                         cudaFuncAttributeMaxDynamicSharedMemorySize, DYN_SMEM);
    cudaFuncSetAttribute(ff_mma_kernel,
                         cudaFuncAttributeMaxDynamicSharedMemorySize, DYN_SMEM);
    cudaFuncSetAttribute(attn_mma_kernel,
                         cudaFuncAttributeMaxDynamicSharedMemorySize, ATT_SMEM);

    // Q/K/V projections: 64x128 tiles -> grid (4, 64, 3)
    proj3_mma_kernel<<<dim3(4, 64, 3), 256, DYN_SMEM>>>(query, key, value,
                                                        wq_w, wq_b, wk_w, wk_b,
                                                        wv_w, wv_b);
    attn_mma_kernel<<<dim3(16, NHEAD, BB), 128, ATT_SMEM>>>(rel, seq_len, lex_num);
    // Output projection: grid (4, 64) = 256 CTAs (>1 wave now)
    ff_mma_kernel<<<dim3(4, 64), 256, DYN_SMEM>>>(ff_w, ff_b, out);
}

// round 8
// speedup vs baseline: 3.4660x; 1.2687x over previous
#include <cuda_runtime.h>
#include <math.h>
#include <stdint.h>

// Problem constants
#define BB 4
#define LL 1024
#define HH 512
#define NHEAD 8
#define DD 64

// Scratch (device globals — no allocation allowed)
__device__ float g_q[BB * LL * HH];
__device__ float g_k[BB * LL * HH];
__device__ float g_v[BB * LL * HH];
__device__ float g_att[BB * LL * HH];

// ===========================================================================
// Helpers
// ===========================================================================
__device__ __forceinline__ uint32_t smem_u32(const void* p) {
    return (uint32_t)__cvta_generic_to_shared(p);
}
__device__ __forceinline__ void cp_async16(uint32_t dst, const void* src) {
    asm volatile("cp.async.cg.shared.global [%0], [%1], 16;"
                 :: "r"(dst), "l"(src) : "memory");
}
#define CP_COMMIT() asm volatile("cp.async.commit_group;" ::: "memory")

__device__ __forceinline__ uint32_t f2tf32(float x) {
    uint32_t r;
    asm("cvt.rna.tf32.f32 %0, %1;" : "=r"(r) : "f"(x));
    return r;
}
// pack two floats into f16x2: lo half = first arg, hi half = second arg
__device__ __forceinline__ uint32_t pack_h2(float lo, float hi) {
    uint32_t r;
    asm("cvt.rn.f16x2.f32 %0, %1, %2;" : "=r"(r) : "f"(hi), "f"(lo));
    return r;
}
__device__ __forceinline__ void mma_tf32(float* d, const uint32_t* a, const uint32_t* b) {
    asm volatile(
        "mma.sync.aligned.m16n8k8.row.col.f32.tf32.tf32.f32 "
        "{%0,%1,%2,%3}, {%4,%5,%6,%7}, {%8,%9}, {%0,%1,%2,%3};"
        : "+f"(d[0]), "+f"(d[1]), "+f"(d[2]), "+f"(d[3])
        : "r"(a[0]), "r"(a[1]), "r"(a[2]), "r"(a[3]), "r"(b[0]), "r"(b[1]));
}
__device__ __forceinline__ void mma_f16(float* d, const uint32_t* a, const uint32_t* b) {
    asm volatile(
        "mma.sync.aligned.m16n8k16.row.col.f32.f16.f16.f32 "
        "{%0,%1,%2,%3}, {%4,%5,%6,%7}, {%8,%9}, {%0,%1,%2,%3};"
        : "+f"(d[0]), "+f"(d[1]), "+f"(d[2]), "+f"(d[3])
        : "r"(a[0]), "r"(a[1]), "r"(a[2]), "r"(a[3]), "r"(b[0]), "r"(b[1]));
}

// ===========================================================================
// fp16 mma.sync GEMM:  Y[M,512] = X[M,512] @ W[512,512]^T + bias
// CTA tile 64x128 (3 CTAs/SM), 8 warps (2x4), warp tile 32x32, BK=32,
// double-buffered cp.async (fp32 operands in smem; converted to f16x2 at
// fragment build via LDS.64 + cvt.rn.f16x2). m16n8k16 = 2x MACs/instr vs
// tf32, same 11-bit significand. Pitch 40: frag LDS.64 super-bank = 4*lr+lc
// -> conflict-free.
// ===========================================================================
#define BK 32
#define PITCH 40
#define A_STAGE (64 * PITCH)                       // 2560 floats
#define B_STAGE (128 * PITCH)                      // 5120 floats
#define DYN_SMEM ((2 * A_STAGE + 2 * B_STAGE) * 4) // 61440 B

__device__ __forceinline__ void gemm_mma_body(
    const float* __restrict__ X, const float* __restrict__ W,
    const float* __restrict__ bias, float* __restrict__ Y,
    int bx, int by)
{
    extern __shared__ float sm[];
    float* As[2] = { sm,               sm + A_STAGE };
    float* Bs[2] = { sm + 2 * A_STAGE, sm + 2 * A_STAGE + B_STAGE };

    const int tid  = threadIdx.x;
    const int w    = tid >> 5;
    const int lane = tid & 31;
    const int lr   = lane >> 2;        // 0..7
    const int lc   = lane & 3;         // 0..3
    const int wm   = (w >> 2) * 32;    // warp m offset (0/32)
    const int wn   = (w & 3) * 32;     // warp n offset (0..96)
    const int row0 = by * 64;
    const int col0 = bx * 128;

    float acc[2][4][4];
#pragma unroll
    for (int i = 0; i < 2; i++)
#pragma unroll
        for (int j = 0; j < 4; j++)
#pragma unroll
            for (int t = 0; t < 4; t++) acc[i][j][t] = 0.f;

    // ---- stage loader: A = 64x32 (512 f4 chunks), B = 128x32 (1024 f4)
#define LOAD_STAGE(IT)                                                        \
    do {                                                                      \
        const int s_  = (IT) & 1;                                             \
        const int k0_ = (IT) * BK;                                            \
        _Pragma("unroll")                                                     \
        for (int p = 0; p < 2; p++) {                                         \
            int id = tid + (p << 8);                                          \
            int r = id >> 3, c = id & 7;                                      \
            cp_async16(smem_u32(&As[s_][r * PITCH + c * 4]),                  \
                       &X[(size_t)(row0 + r) * 512 + k0_ + c * 4]);           \
        }                                                                     \
        _Pragma("unroll")                                                     \
        for (int p = 0; p < 4; p++) {                                         \
            int id = tid + (p << 8);                                          \
            int r = id >> 3, c = id & 7;                                      \
            cp_async16(smem_u32(&Bs[s_][r * PITCH + c * 4]),                  \
                       &W[(size_t)(col0 + r) * 512 + k0_ + c * 4]);           \
        }                                                                     \
        CP_COMMIT();                                                          \
    } while (0)

    LOAD_STAGE(0);

    for (int it = 0; it < 16; it++) {
        if (it + 1 < 16) {
            LOAD_STAGE(it + 1);
            asm volatile("cp.async.wait_group 1;" ::: "memory");
        } else {
            asm volatile("cp.async.wait_group 0;" ::: "memory");
        }
        __syncthreads();

        const float* A = As[it & 1];
        const float* B = Bs[it & 1];
#pragma unroll
        for (int ks = 0; ks < 2; ks++) {           // two k=16 steps per BK=32
            const int kb = ks * 16 + 2 * lc;
            uint32_t a[2][4];
#pragma unroll
            for (int i = 0; i < 2; i++) {
                const float* ap = &A[(wm + i * 16 + lr) * PITCH + kb];
                float2 v0 = *reinterpret_cast<const float2*>(ap);
                float2 v1 = *reinterpret_cast<const float2*>(ap + 8 * PITCH);
                float2 v2 = *reinterpret_cast<const float2*>(ap + 8);
                float2 v3 = *reinterpret_cast<const float2*>(ap + 8 * PITCH + 8);
                a[i][0] = pack_h2(v0.x, v0.y);
                a[i][1] = pack_h2(v1.x, v1.y);
                a[i][2] = pack_h2(v2.x, v2.y);
                a[i][3] = pack_h2(v3.x, v3.y);
            }
#pragma unroll
            for (int j = 0; j < 4; j++) {
                const float* bp = &B[(wn + j * 8 + lr) * PITCH + kb];
                float2 w0 = *reinterpret_cast<const float2*>(bp);
                float2 w1 = *reinterpret_cast<const float2*>(bp + 8);
                uint32_t bb[2] = { pack_h2(w0.x, w0.y), pack_h2(w1.x, w1.y) };
                mma_f16(acc[0][j], a[0], bb);
                mma_f16(acc[1][j], a[1], bb);
            }
        }
        __syncthreads();
    }

    // ---- epilogue: +bias, float2 stores (D frag: rows lr/lr+8, cols 2lc,2lc+1)
#pragma unroll
    for (int j = 0; j < 4; j++) {
        const int col = col0 + wn + j * 8 + lc * 2;
        const float2 bb = *reinterpret_cast<const float2*>(&bias[col]);
#pragma unroll
        for (int i = 0; i < 2; i++) {
            const int r0 = row0 + wm + i * 16 + lr;
            float2 o0 = { acc[i][j][0] + bb.x, acc[i][j][1] + bb.y };
            float2 o1 = { acc[i][j][2] + bb.x, acc[i][j][3] + bb.y };
            *reinterpret_cast<float2*>(&Y[(size_t)r0 * 512 + col]) = o0;
            *reinterpret_cast<float2*>(&Y[(size_t)(r0 + 8) * 512 + col]) = o1;
        }
    }
#undef LOAD_STAGE
}

__global__ __launch_bounds__(256, 3)
void proj3_mma_kernel(const float* __restrict__ q_in, const float* __restrict__ k_in,
                      const float* __restrict__ v_in,
                      const float* __restrict__ wq, const float* __restrict__ bq,
                      const float* __restrict__ wk, const float* __restrict__ bk,
                      const float* __restrict__ wv, const float* __restrict__ bv)
{
    const float* X; const float* W; const float* bias; float* Y;
    if (blockIdx.z == 0)      { X = q_in; W = wq; bias = bq; Y = g_q; }
    else if (blockIdx.z == 1) { X = k_in; W = wk; bias = bk; Y = g_k; }
    else                      { X = v_in; W = wv; bias = bv; Y = g_v; }
    gemm_mma_body(X, W, bias, Y, blockIdx.x, blockIdx.y);
}

__global__ __launch_bounds__(256, 3)
void ff_mma_kernel(const float* __restrict__ w, const float* __restrict__ bias,
                   float* __restrict__ out)
{
    gemm_mma_body(g_att, w, bias, out, blockIdx.x, blockIdx.y);
}

// ===========================================================================
// Tensor-core fused attention (UNCHANGED from round-5/6 passing version).
// CTA = 64 q-rows x (b,h). 4 warps, each owns 16 q-rows -> warp-private
// softmax. K/V double-buffered cp.async; P as tf32 bits in warp-private smem.
// Masked key tiles skipped entirely.
// ===========================================================================
#define KPITCH 68   // bank: 4*lr+lc  -> conflict-free B/A frag reads
#define VPITCH 72   // bank: 8*lc+lr  -> conflict-free B frag reads
#define KS_F (64 * KPITCH)
#define VS_F (64 * VPITCH)
#define ATT_SMEM ((2 * KS_F + 2 * VS_F + 64 * KPITCH) * 4)   // 89088 B

__global__ __launch_bounds__(128, 2)
void attn_mma_kernel(const float* __restrict__ rel,
                     const int* __restrict__ seq_len,
                     const int* __restrict__ lex_num)
{
    extern __shared__ float asmem[];
    float* Ks = asmem;                       // [2][64][KPITCH]
    float* Vs = asmem + 2 * KS_F;            // [2][64][VPITCH]
    uint32_t* Ps = (uint32_t*)(asmem + 2 * KS_F + 2 * VS_F);  // [64][KPITCH] tf32

    const int qt = blockIdx.x;
    const int h  = blockIdx.y;
    const int b  = blockIdx.z;
    const int tid  = threadIdx.x;
    const int w    = tid >> 5;
    const int lane = tid & 31;
    const int lr   = lane >> 2;       // 0..7
    const int lc   = lane & 3;        // 0..3

    const int len = seq_len[b] + lex_num[b];
    int ntiles = (len + 63) >> 6;
    if (ntiles > 16) ntiles = 16;

    const float* Qg   = g_q + ((size_t)b * LL + qt * 64) * HH + h * DD;
    const float* Kg   = g_k + (size_t)b * LL * HH + h * DD;
    const float* Vg   = g_v + (size_t)b * LL * HH + h * DD;
    const float* relb = rel + (((size_t)b * NHEAD + h) * LL + (size_t)qt * 64) * LL;

    const int r0 = w * 16 + lr;       // this thread's first q-row (local)

    // Q fragments, converted to tf32 once (A-frag layout for m16n8k8)
    uint32_t qf[8][4];
#pragma unroll
    for (int kk = 0; kk < 8; kk++) {
        qf[kk][0] = f2tf32(Qg[(size_t)r0 * HH + kk * 8 + lc]);
        qf[kk][1] = f2tf32(Qg[(size_t)(r0 + 8) * HH + kk * 8 + lc]);
        qf[kk][2] = f2tf32(Qg[(size_t)r0 * HH + kk * 8 + lc + 4]);
        qf[kk][3] = f2tf32(Qg[(size_t)(r0 + 8) * HH + kk * 8 + lc + 4]);
    }

    float m_i[2] = { -1e30f, -1e30f };
    float l_i[2] = { 0.f, 0.f };
    float oacc[8][4];
#pragma unroll
    for (int j = 0; j < 8; j++)
#pragma unroll
        for (int t = 0; t < 4; t++) oacc[j][t] = 0.f;

#define ATT_LOAD(KT)                                                          \
    do {                                                                      \
        const int s_ = (KT) & 1;                                              \
        const float* ksrc = Kg + (size_t)(KT) * 64 * HH;                      \
        const float* vsrc = Vg + (size_t)(KT) * 64 * HH;                      \
        float* kd = Ks + s_ * KS_F;                                           \
        float* vd = Vs + s_ * VS_F;                                           \
        _Pragma("unroll")                                                     \
        for (int p = 0; p < 8; p++) {                                         \
            int id = tid + (p << 7);                                          \
            int r = id >> 4, c = id & 15;                                     \
            cp_async16(smem_u32(kd + r * KPITCH + c * 4),                     \
                       ksrc + (size_t)r * HH + c * 4);                        \
            cp_async16(smem_u32(vd + r * VPITCH + c * 4),                     \
                       vsrc + (size_t)r * HH + c * 4);                        \
        }                                                                     \
        CP_COMMIT();                                                          \
    } while (0)

    ATT_LOAD(0);

    for (int kt = 0; kt < ntiles; kt++) {
        asm volatile("cp.async.wait_group 0;" ::: "memory");
        __syncthreads();                          // tile kt visible; prev buffer free
        if (kt + 1 < ntiles) ATT_LOAD(kt + 1);    // overlap next load with compute

        const float* K0 = Ks + (kt & 1) * KS_F;
        const float* V0 = Vs + (kt & 1) * VS_F;

        // ---- S = Q @ K^T  (warp: 16 x 64, k=64)
        float sacc[8][4];
#pragma unroll
        for (int j = 0; j < 8; j++)
#pragma unroll
            for (int t = 0; t < 4; t++) sacc[j][t] = 0.f;

#pragma unroll
        for (int kk = 0; kk < 8; kk++) {
#pragma unroll
            for (int j = 0; j < 8; j++) {
                uint32_t bb[2];
                const float* kp = &K0[(j * 8 + lr) * KPITCH + kk * 8 + lc];
                bb[0] = f2tf32(kp[0]);
                bb[1] = f2tf32(kp[4]);
                mma_tf32(sacc[j], qf[kk], bb);
            }
        }

        // ---- rel bias + scale + padding mask
        const int colbase = kt * 64;
        float2 rl0[8], rl1[8];
#pragma unroll
        for (int j = 0; j < 8; j++) {
            rl0[j] = *reinterpret_cast<const float2*>(
                &relb[(size_t)r0 * LL + colbase + j * 8 + 2 * lc]);
            rl1[j] = *reinterpret_cast<const float2*>(
                &relb[(size_t)(r0 + 8) * LL + colbase + j * 8 + 2 * lc]);
        }
#pragma unroll
        for (int j = 0; j < 8; j++) {
            const int c0 = colbase + j * 8 + 2 * lc;
            sacc[j][0] = (c0     < len) ? sacc[j][0] * 0.125f + rl0[j].x : -1e30f;
            sacc[j][1] = (c0 + 1 < len) ? sacc[j][1] * 0.125f + rl0[j].y : -1e30f;
            sacc[j][2] = (c0     < len) ? sacc[j][2] * 0.125f + rl1[j].x : -1e30f;
            sacc[j][3] = (c0 + 1 < len) ? sacc[j][3] * 0.125f + rl1[j].y : -1e30f;
        }

        // ---- online softmax (two rows per thread; reduce over 4 lanes)
#pragma unroll
        for (int t = 0; t < 2; t++) {
            float mx = -1e30f;
#pragma unroll
            for (int j = 0; j < 8; j++)
                mx = fmaxf(mx, fmaxf(sacc[j][2 * t], sacc[j][2 * t + 1]));
            mx = fmaxf(mx, __shfl_xor_sync(0xffffffffu, mx, 1));
            mx = fmaxf(mx, __shfl_xor_sync(0xffffffffu, mx, 2));
            const float mnew = fmaxf(m_i[t], mx);
            const float corr = __expf(m_i[t] - mnew);
            m_i[t] = mnew;
            float sum = 0.f;
#pragma unroll
            for (int j = 0; j < 8; j++) {
                sacc[j][2 * t]     = __expf(sacc[j][2 * t] - mnew);
                sacc[j][2 * t + 1] = __expf(sacc[j][2 * t + 1] - mnew);
                sum += sacc[j][2 * t] + sacc[j][2 * t + 1];
            }
            sum += __shfl_xor_sync(0xffffffffu, sum, 1);
            sum += __shfl_xor_sync(0xffffffffu, sum, 2);
            l_i[t] = l_i[t] * corr + sum;
#pragma unroll
            for (int j = 0; j < 8; j++) {
                oacc[j][2 * t]     *= corr;
                oacc[j][2 * t + 1] *= corr;
            }
        }

        // ---- P to warp-private smem slice (as tf32 bits)
#pragma unroll
        for (int j = 0; j < 8; j++) {
            uint32_t* p0 = Ps + (size_t)r0 * KPITCH + j * 8 + 2 * lc;
            uint32_t* p1 = Ps + (size_t)(r0 + 8) * KPITCH + j * 8 + 2 * lc;
            p0[0] = f2tf32(sacc[j][0]); p0[1] = f2tf32(sacc[j][1]);
            p1[0] = f2tf32(sacc[j][2]); p1[1] = f2tf32(sacc[j][3]);
        }
        __syncwarp();

        // ---- O += P @ V  (warp: 16 x 64, k=64)
#pragma unroll
        for (int kk = 0; kk < 8; kk++) {
            uint32_t af[4];
            af[0] = Ps[(size_t)r0 * KPITCH + kk * 8 + lc];
            af[1] = Ps[(size_t)(r0 + 8) * KPITCH + kk * 8 + lc];
            af[2] = Ps[(size_t)r0 * KPITCH + kk * 8 + lc + 4];
            af[3] = Ps[(size_t)(r0 + 8) * KPITCH + kk * 8 + lc + 4];
#pragma unroll
            for (int j = 0; j < 8; j++) {
                uint32_t bb[2];
                bb[0] = f2tf32(V0[(kk * 8 + lc) * VPITCH + j * 8 + lr]);
                bb[1] = f2tf32(V0[(kk * 8 + lc + 4) * VPITCH + j * 8 + lr]);
                mma_tf32(oacc[j], af, bb);
            }
        }
        __syncwarp();   // Ps reads done before next iteration overwrites
    }

    // ---- normalize + store
    float* Og = g_att + ((size_t)b * LL + qt * 64) * HH + h * DD;
    const float inv0 = 1.0f / l_i[0];
    const float inv1 = 1.0f / l_i[1];
#pragma unroll
    for (int j = 0; j < 8; j++) {
        float2 o0 = { oacc[j][0] * inv0, oacc[j][1] * inv0 };
        float2 o1 = { oacc[j][2] * inv1, oacc[j][3] * inv1 };
        *reinterpret_cast<float2*>(&Og[(size_t)r0 * HH + j * 8 + 2 * lc]) = o0;
        *reinterpret_cast<float2*>(&Og[(size_t)(r0 + 8) * HH + j * 8 + 2 * lc]) = o1;
    }
#undef ATT_LOAD
}

// ---------------------------------------------------------------------------
extern "C" void kernel_launch(void* const* d_in, const int* in_sizes, int n_in,
                              void* d_out, int out_size)
{
    const float* key   = (const float*)d_in[0];
    const float* query = (const float*)d_in[1];
    const float* value = (const float*)d_in[2];
    const float* rel   = (const float*)d_in[3];
    const float* wk_w  = (const float*)d_in[4];
    const float* wk_b  = (const float*)d_in[5];
    const float* wq_w  = (const float*)d_in[6];
    const float* wq_b  = (const float*)d_in[7];
    const float* wv_w  = (const float*)d_in[8];
    const float* wv_b  = (const float*)d_in[9];
    const float* ff_w  = (const float*)d_in[10];
    const float* ff_b  = (const float*)d_in[11];
    const int* seq_len = (const int*)d_in[12];
    const int* lex_num = (const int*)d_in[13];
    float* out = (float*)d_out;

    cudaFuncSetAttribute(proj3_mma_kernel,
                         cudaFuncAttributeMaxDynamicSharedMemorySize, DYN_SMEM);
    cudaFuncSetAttribute(ff_mma_kernel,
                         cudaFuncAttributeMaxDynamicSharedMemorySize, DYN_SMEM);
    cudaFuncSetAttribute(attn_mma_kernel,
                         cudaFuncAttributeMaxDynamicSharedMemorySize, ATT_SMEM);

    // Q/K/V projections: 64x128 tiles -> grid (4, 64, 3)
    proj3_mma_kernel<<<dim3(4, 64, 3), 256, DYN_SMEM>>>(query, key, value,
                                                        wq_w, wq_b, wk_w, wk_b,
                                                        wv_w, wv_b);
    attn_mma_kernel<<<dim3(16, NHEAD, BB), 128, ATT_SMEM>>>(rel, seq_len, lex_num);
    // Output projection: grid (4, 64) = 256 CTAs
    ff_mma_kernel<<<dim3(4, 64), 256, DYN_SMEM>>>(ff_w, ff_b, out);
}